// round 14
// baseline (speedup 1.0000x reference)
#include <cuda_runtime.h>
#include <cstdint>

#define B 8
#define C 128
#define H 256
#define W 256
#define HW (H*W)        // 65536
#define HW4 (HW/4)      // 16384

__device__ float g_pooled[B * HW];
__device__ float g_attn[B * HW];

// ---------------------------------------------------------------------------
// poolPair v3: batches b0, b0+1. grid 256 x 256. Long 64-load bodies.
// Warp layout: 16 float4-pixels x 2 channel-halves.
//   lanes 0..15  -> pixels p0..p15, channels [0,64)
//   lanes 16..31 -> pixels p0..p15, channels [64,128)
// Per thread: 64 loads in 4-deep MLP groups; combine via one shfl_xor(16);
// lanes 0..15 store. No smem, no __syncthreads.
// ---------------------------------------------------------------------------
__global__ void __launch_bounds__(256) pool_pair_kernel(
        const float* __restrict__ x, int b0)
{
    const int wid  = blockIdx.x * 8 + (threadIdx.x >> 5);  // 0..2047
    const int lane = threadIdx.x & 31;
    const int half = lane >> 4;            // 0 or 1 (channel half)
    const int pw   = lane & 15;            // pixel within warp
    const int b    = b0 + (wid >> 10);     // 1024 warps per batch
    const int hw4  = (wid & 1023) * 16 + pw;

    const float4* p = reinterpret_cast<const float4*>(x)
                      + ((size_t)b * C + (size_t)half * 64) * HW4 + hw4;

    float4 m = make_float4(-3.4e38f, -3.4e38f, -3.4e38f, -3.4e38f);
    #pragma unroll 4
    for (int k = 0; k < 64; k += 4) {
        float4 v0 = p[(size_t)(k + 0) * HW4];
        float4 v1 = p[(size_t)(k + 1) * HW4];
        float4 v2 = p[(size_t)(k + 2) * HW4];
        float4 v3 = p[(size_t)(k + 3) * HW4];
        m.x = fmaxf(fmaxf(m.x, v0.x), fmaxf(v1.x, fmaxf(v2.x, v3.x)));
        m.y = fmaxf(fmaxf(m.y, v0.y), fmaxf(v1.y, fmaxf(v2.y, v3.y)));
        m.z = fmaxf(fmaxf(m.z, v0.z), fmaxf(v1.z, fmaxf(v2.z, v3.z)));
        m.w = fmaxf(fmaxf(m.w, v0.w), fmaxf(v1.w, fmaxf(v2.w, v3.w)));
    }

    // combine the two channel halves (lane i <-> lane i+16)
    m.x = fmaxf(m.x, __shfl_xor_sync(0xffffffffu, m.x, 16));
    m.y = fmaxf(m.y, __shfl_xor_sync(0xffffffffu, m.y, 16));
    m.z = fmaxf(m.z, __shfl_xor_sync(0xffffffffu, m.z, 16));
    m.w = fmaxf(m.w, __shfl_xor_sync(0xffffffffu, m.w, 16));

    if (half == 0)
        reinterpret_cast<float4*>(g_pooled)[(size_t)b * HW4 + hw4] = m;
}

// ---------------------------------------------------------------------------
// convPair: batches b0, b0+1. grid (4,16,2), block 256.
// ---------------------------------------------------------------------------
#define TW 64
#define TH 16

__global__ void __launch_bounds__(256) conv_pair_kernel(
        const float* __restrict__ cw, const float* __restrict__ cb, int b0)
{
    __shared__ float s[TH + 6][TW + 8];
    const int b   = b0 + blockIdx.z;
    const int tx0 = blockIdx.x * TW;
    const int ty0 = blockIdx.y * TH;
    const float* pb = g_pooled + b * HW;

    for (int i = threadIdx.x; i < (TH + 6) * (TW + 6); i += 256) {
        int ly = i / (TW + 6);
        int lx = i - ly * (TW + 6);
        int gy = ty0 + ly - 3;
        int gx = tx0 + lx - 3;
        float v = 0.0f;
        if (gy >= 0 && gy < H && gx >= 0 && gx < W) v = pb[gy * W + gx];
        s[ly][lx] = v;
    }
    __syncthreads();

    float wr[49];
    #pragma unroll
    for (int i = 0; i < 49; ++i) wr[i] = __ldg(&cw[i]);
    const float bias = __ldg(&cb[0]);

    const int lx  = threadIdx.x & (TW - 1);
    const int ly0 = threadIdx.x >> 6;

    #pragma unroll
    for (int r = 0; r < TH; r += 4) {
        const int ly = ly0 + r;
        float acc = bias;
        #pragma unroll
        for (int i = 0; i < 7; ++i)
            #pragma unroll
            for (int j = 0; j < 7; ++j)
                acc = fmaf(s[ly + i][lx + j], wr[i * 7 + j], acc);
        float sg = 1.0f / (1.0f + __expf(-acc));
        g_attn[b * HW + (ty0 + ly) * W + tx0 + lx] = sg;
    }
}

// ---------------------------------------------------------------------------
// mulPair: batches b0, b0+1. grid 16384, block 256, one float4 per thread.
// x reads hit L2 (left by poolPair); __stcs writes stream out.
// ---------------------------------------------------------------------------
__global__ void __launch_bounds__(256) mul_pair_kernel(
        const float* __restrict__ x, float* __restrict__ out, int b0)
{
    size_t i = (size_t)blockIdx.x * blockDim.x + threadIdx.x;  // f4 idx in pair
    int hw4 = (int)(i & (HW4 - 1));
    int bi  = (int)(i >> 21);
    size_t gi = ((size_t)(b0 + bi)) * C * HW4 + (i & ((1u << 21) - 1));

    float4 a = __ldg(reinterpret_cast<const float4*>(g_attn)
                     + (size_t)(b0 + bi) * HW4 + hw4);
    float4 v = __ldcs(reinterpret_cast<const float4*>(x) + gi);
    v.x *= a.x; v.y *= a.y; v.z *= a.z; v.w *= a.w;
    __stcs(reinterpret_cast<float4*>(out) + gi, v);
}

// ---------------------------------------------------------------------------
extern "C" void kernel_launch(void* const* d_in, const int* in_sizes, int n_in,
                              void* d_out, int out_size) {
    const float* x  = (const float*)d_in[0];
    const float* cw = (const float*)d_in[1];
    const float* cb = (const float*)d_in[2];
    float* out = (float*)d_out;

    dim3 gc(W / TW, H / TH, 2);
    for (int p = 0; p < 4; ++p) {
        const int b0 = 2 * p;
        pool_pair_kernel<<<256, 256>>>(x, b0);
        conv_pair_kernel<<<gc, 256>>>(cw, cb, b0);
        mul_pair_kernel<<<2 * C * HW4 / 256, 256>>>(x, out, b0);
    }
}

// round 16
// speedup vs baseline: 1.0332x; 1.0332x over previous
#include <cuda_runtime.h>
#include <cstdint>

#define B 8
#define C 128
#define H 256
#define W 256
#define HW (H*W)        // 65536
#define HW4 (HW/4)      // 16384

__device__ float g_pooled[B * HW];
__device__ float g_attn[B * HW];
__device__ int   g_pool_done[B];   // 256 pool blocks per batch

__global__ void reset_kernel() {
    #pragma unroll
    for (int i = 0; i < B; ++i) g_pool_done[i] = 0;
}

// ---------------------------------------------------------------------------
// poolConvPair: batches b0, b0+1. grid 640 x 256.
//   blocks [0,512):   pool (R8 body: 64 f4-pixels x 4 ch-groups, smem reduce)
//   blocks [512,640): conv 64x16 tiles; spin until their batch's pool done.
// Pool blocks never wait -> deadlock-free. Plain x loads keep x in L2 for
// the mulPair launch that follows.
// ---------------------------------------------------------------------------
#define TW 64
#define TH 16

__global__ void __launch_bounds__(256) poolconv_pair_kernel(
        const float* __restrict__ x,
        const float* __restrict__ cw, const float* __restrict__ cb, int b0)
{
    const int tid = threadIdx.x;

    if (blockIdx.x < 512) {
        // ---------------- pool role ----------------
        __shared__ float4 red[256];
        const int rid   = blockIdx.x;
        const int b     = b0 + (rid >> 8);
        const int inner = rid & 255;
        const int grp = tid >> 6;          // 0..3 (32 channels each)
        const int pix = tid & 63;
        const int hw4 = inner * 64 + pix;

        const float4* p = reinterpret_cast<const float4*>(x)
                          + ((size_t)b * C + (size_t)grp * 32) * HW4 + hw4;
        float4 m = p[0];
        #pragma unroll 8
        for (int c = 1; c < 32; ++c) {
            float4 v = p[(size_t)c * HW4];
            m.x = fmaxf(m.x, v.x);
            m.y = fmaxf(m.y, v.y);
            m.z = fmaxf(m.z, v.z);
            m.w = fmaxf(m.w, v.w);
        }
        red[tid] = m;
        __syncthreads();

        if (grp == 0) {
            float4 a  = red[pix];
            float4 b1 = red[64 + pix];
            float4 c1 = red[128 + pix];
            float4 d1 = red[192 + pix];
            a.x = fmaxf(fmaxf(a.x, b1.x), fmaxf(c1.x, d1.x));
            a.y = fmaxf(fmaxf(a.y, b1.y), fmaxf(c1.y, d1.y));
            a.z = fmaxf(fmaxf(a.z, b1.z), fmaxf(c1.z, d1.z));
            a.w = fmaxf(fmaxf(a.w, b1.w), fmaxf(c1.w, d1.w));
            reinterpret_cast<float4*>(g_pooled)[(size_t)b * HW4 + hw4] = a;
        }
        __syncthreads();
        if (tid == 0) { __threadfence(); atomicAdd(&g_pool_done[b], 1); }
    } else {
        // ---------------- conv role (spins on pool done) ----------------
        __shared__ float s[TH + 6][TW + 8];
        const int u   = blockIdx.x - 512;      // 0..127
        const int b   = b0 + (u >> 6);
        const int t64 = u & 63;
        const int tx0 = (t64 & 3) * TW;
        const int ty0 = (t64 >> 2) * TH;

        if (tid == 0) {
            while (*(volatile int*)&g_pool_done[b] < 256) __nanosleep(64);
            __threadfence();
        }
        __syncthreads();

        const float* pb = g_pooled + b * HW;
        for (int i = tid; i < (TH + 6) * (TW + 6); i += 256) {
            int ly = i / (TW + 6);
            int lx = i - ly * (TW + 6);
            int gy = ty0 + ly - 3;
            int gx = tx0 + lx - 3;
            float v = 0.0f;
            if (gy >= 0 && gy < H && gx >= 0 && gx < W) v = pb[gy * W + gx];
            s[ly][lx] = v;
        }
        __syncthreads();

        float wr[49];
        #pragma unroll
        for (int i = 0; i < 49; ++i) wr[i] = __ldg(&cw[i]);
        const float bias = __ldg(&cb[0]);

        const int lx  = tid & (TW - 1);
        const int ly0 = tid >> 6;

        #pragma unroll
        for (int r = 0; r < TH; r += 4) {
            const int ly = ly0 + r;
            float acc = bias;
            #pragma unroll
            for (int i = 0; i < 7; ++i)
                #pragma unroll
                for (int j = 0; j < 7; ++j)
                    acc = fmaf(s[ly + i][lx + j], wr[i * 7 + j], acc);
            float sg = 1.0f / (1.0f + __expf(-acc));
            g_attn[b * HW + (ty0 + ly) * W + tx0 + lx] = sg;
        }
    }
}

// ---------------------------------------------------------------------------
// mulPair v2: batches b0, b0+1. grid 4096 x 256.
// Thread = one f4 pixel x 4 consecutive channels: 1 attn load amortized over
// 4 (ldcs + stcs) pairs -> 9 mem ops / 64B (was 12). x reads hit L2.
// ---------------------------------------------------------------------------
__global__ void __launch_bounds__(256) mul_pair_kernel(
        const float* __restrict__ x, float* __restrict__ out, int b0)
{
    const int tt   = blockIdx.x * 256 + threadIdx.x;   // < 2^20
    const int hw4  = tt & (HW4 - 1);
    const int rest = tt >> 14;             // 0..63
    const int cg   = rest & 31;            // channel group (4 ch)
    const int bi   = rest >> 5;            // 0 or 1
    const int b    = b0 + bi;

    const float4 a = __ldg(reinterpret_cast<const float4*>(g_attn)
                           + (size_t)b * HW4 + hw4);
    const float4* xp = reinterpret_cast<const float4*>(x)
                       + ((size_t)b * C + cg * 4) * HW4 + hw4;
    float4* op = reinterpret_cast<float4*>(out)
                 + ((size_t)b * C + cg * 4) * HW4 + hw4;

    float4 v0 = __ldcs(xp);
    float4 v1 = __ldcs(xp + HW4);
    float4 v2 = __ldcs(xp + 2 * HW4);
    float4 v3 = __ldcs(xp + 3 * HW4);
    v0.x *= a.x; v0.y *= a.y; v0.z *= a.z; v0.w *= a.w;
    v1.x *= a.x; v1.y *= a.y; v1.z *= a.z; v1.w *= a.w;
    v2.x *= a.x; v2.y *= a.y; v2.z *= a.z; v2.w *= a.w;
    v3.x *= a.x; v3.y *= a.y; v3.z *= a.z; v3.w *= a.w;
    __stcs(op, v0);
    __stcs(op + HW4, v1);
    __stcs(op + 2 * HW4, v2);
    __stcs(op + 3 * HW4, v3);
}

// ---------------------------------------------------------------------------
extern "C" void kernel_launch(void* const* d_in, const int* in_sizes, int n_in,
                              void* d_out, int out_size) {
    const float* x  = (const float*)d_in[0];
    const float* cw = (const float*)d_in[1];
    const float* cb = (const float*)d_in[2];
    float* out = (float*)d_out;

    reset_kernel<<<1, 1>>>();
    for (int p = 0; p < 4; ++p) {
        const int b0 = 2 * p;
        poolconv_pair_kernel<<<640, 256>>>(x, cw, cb, b0);
        mul_pair_kernel<<<4096, 256>>>(x, out, b0);
    }
}

// round 17
// speedup vs baseline: 1.1018x; 1.0663x over previous
#include <cuda_runtime.h>
#include <cstdint>

#define B 8
#define C 128
#define H 256
#define W 256
#define HW (H*W)        // 65536
#define HW4 (HW/4)      // 16384

__device__ float g_pooled[B * HW];
__device__ float g_attn[B * HW];

// ---------------------------------------------------------------------------
// poolPair: batches b0, b0+1. grid 512, block 256. (R10's measured version:
// 13.9us, regs 32.) Block = (batch, 64 f4-pixels), 4-way channel split,
// smem reduce. Plain loads leave x_pair L2-resident for mulPair.
// ---------------------------------------------------------------------------
__global__ void __launch_bounds__(256) pool_pair_kernel(
        const float* __restrict__ x, int b0)
{
    __shared__ float4 red[256];
    const int rid   = blockIdx.x;
    const int b     = b0 + (rid >> 8);
    const int inner = rid & 255;
    const int tid = threadIdx.x;
    const int grp = tid >> 6;
    const int pix = tid & 63;
    const int hw4 = inner * 64 + pix;

    const float4* p = reinterpret_cast<const float4*>(x)
                      + ((size_t)b * C + (size_t)grp * 32) * HW4 + hw4;
    float4 m = p[0];
    #pragma unroll 8
    for (int c = 1; c < 32; ++c) {
        float4 v = p[(size_t)c * HW4];
        m.x = fmaxf(m.x, v.x);
        m.y = fmaxf(m.y, v.y);
        m.z = fmaxf(m.z, v.z);
        m.w = fmaxf(m.w, v.w);
    }
    red[tid] = m;
    __syncthreads();

    if (grp == 0) {
        float4 a  = red[pix];
        float4 b1 = red[64 + pix];
        float4 c1 = red[128 + pix];
        float4 d1 = red[192 + pix];
        a.x = fmaxf(fmaxf(a.x, b1.x), fmaxf(c1.x, d1.x));
        a.y = fmaxf(fmaxf(a.y, b1.y), fmaxf(c1.y, d1.y));
        a.z = fmaxf(fmaxf(a.z, b1.z), fmaxf(c1.z, d1.z));
        a.w = fmaxf(fmaxf(a.w, b1.w), fmaxf(c1.w, d1.w));
        reinterpret_cast<float4*>(g_pooled)[(size_t)b * HW4 + hw4] = a;
    }
}

// ---------------------------------------------------------------------------
// convPair: batches b0, b0+1. grid (4,16,2), block 256. (R10's version.)
// ---------------------------------------------------------------------------
#define TW 64
#define TH 16

__global__ void __launch_bounds__(256) conv_pair_kernel(
        const float* __restrict__ cw, const float* __restrict__ cb, int b0)
{
    __shared__ float s[TH + 6][TW + 8];
    const int b   = b0 + blockIdx.z;
    const int tx0 = blockIdx.x * TW;
    const int ty0 = blockIdx.y * TH;
    const float* pb = g_pooled + b * HW;

    for (int i = threadIdx.x; i < (TH + 6) * (TW + 6); i += 256) {
        int ly = i / (TW + 6);
        int lx = i - ly * (TW + 6);
        int gy = ty0 + ly - 3;
        int gx = tx0 + lx - 3;
        float v = 0.0f;
        if (gy >= 0 && gy < H && gx >= 0 && gx < W) v = pb[gy * W + gx];
        s[ly][lx] = v;
    }
    __syncthreads();

    float wr[49];
    #pragma unroll
    for (int i = 0; i < 49; ++i) wr[i] = __ldg(&cw[i]);
    const float bias = __ldg(&cb[0]);

    const int lx  = threadIdx.x & (TW - 1);
    const int ly0 = threadIdx.x >> 6;

    #pragma unroll
    for (int r = 0; r < TH; r += 4) {
        const int ly = ly0 + r;
        float acc = bias;
        #pragma unroll
        for (int i = 0; i < 7; ++i)
            #pragma unroll
            for (int j = 0; j < 7; ++j)
                acc = fmaf(s[ly + i][lx + j], wr[i * 7 + j], acc);
        float sg = 1.0f / (1.0f + __expf(-acc));
        g_attn[b * HW + (ty0 + ly) * W + tx0 + lx] = sg;
    }
}

// ---------------------------------------------------------------------------
// mulPair v2: batches b0, b0+1. grid 4096 x 256.
// Thread = one f4 pixel x 4 consecutive channels: 1 attn load amortized over
// 4 (ldcs + stcs) pairs -> 9 mem ops / 64B (was 12). x reads hit L2.
// ---------------------------------------------------------------------------
__global__ void __launch_bounds__(256) mul_pair_kernel(
        const float* __restrict__ x, float* __restrict__ out, int b0)
{
    const int tt   = blockIdx.x * 256 + threadIdx.x;   // < 2^20
    const int hw4  = tt & (HW4 - 1);
    const int rest = tt >> 14;             // 0..63
    const int cg   = rest & 31;            // channel group (4 ch)
    const int bi   = rest >> 5;            // 0 or 1
    const int b    = b0 + bi;

    const float4 a = __ldg(reinterpret_cast<const float4*>(g_attn)
                           + (size_t)b * HW4 + hw4);
    const float4* xp = reinterpret_cast<const float4*>(x)
                       + ((size_t)b * C + cg * 4) * HW4 + hw4;
    float4* op = reinterpret_cast<float4*>(out)
                 + ((size_t)b * C + cg * 4) * HW4 + hw4;

    float4 v0 = __ldcs(xp);
    float4 v1 = __ldcs(xp + HW4);
    float4 v2 = __ldcs(xp + 2 * HW4);
    float4 v3 = __ldcs(xp + 3 * HW4);
    v0.x *= a.x; v0.y *= a.y; v0.z *= a.z; v0.w *= a.w;
    v1.x *= a.x; v1.y *= a.y; v1.z *= a.z; v1.w *= a.w;
    v2.x *= a.x; v2.y *= a.y; v2.z *= a.z; v2.w *= a.w;
    v3.x *= a.x; v3.y *= a.y; v3.z *= a.z; v3.w *= a.w;
    __stcs(op, v0);
    __stcs(op + HW4, v1);
    __stcs(op + 2 * HW4, v2);
    __stcs(op + 3 * HW4, v3);
}

// ---------------------------------------------------------------------------
extern "C" void kernel_launch(void* const* d_in, const int* in_sizes, int n_in,
                              void* d_out, int out_size) {
    const float* x  = (const float*)d_in[0];
    const float* cw = (const float*)d_in[1];
    const float* cb = (const float*)d_in[2];
    float* out = (float*)d_out;

    dim3 gc(W / TW, H / TH, 2);
    for (int p = 0; p < 4; ++p) {
        const int b0 = 2 * p;
        pool_pair_kernel<<<512, 256>>>(x, b0);
        conv_pair_kernel<<<gc, 256>>>(cw, cb, b0);
        mul_pair_kernel<<<4096, 256>>>(x, out, b0);
    }
}